// round 17
// baseline (speedup 1.0000x reference)
#include <cuda_runtime.h>
#include <cuda_bf16.h>
#include <cstdint>

#define NUTT 64
#define SEQL 512
#define DIM  256
#define G3   768

// ---------------- scratch (__device__ globals; no allocation) --------------
__device__ float g_gx[(size_t)NUTT * SEQL * G3];     // ~100.7 MB

// ---------------- packed f32x2 helpers (Blackwell FFMA2) -------------------
__device__ __forceinline__ unsigned long long pk2(float x, float y) {
    unsigned long long d;
    asm("mov.b64 %0, {%1, %2};" : "=l"(d) : "f"(x), "f"(y));
    return d;
}
__device__ __forceinline__ float2 upk2(unsigned long long v) {
    float2 r;
    asm("mov.b64 {%0, %1}, %2;" : "=f"(r.x), "=f"(r.y) : "l"(v));
    return r;
}
__device__ __forceinline__ unsigned long long fma2(unsigned long long a,
                                                   unsigned long long b,
                                                   unsigned long long c) {
    unsigned long long d;
    asm("fma.rn.f32x2 %0, %1, %2, %3;" : "=l"(d) : "l"(a), "l"(b), "l"(c));
    return d;
}
__device__ __forceinline__ unsigned smem_u32(const void* p) {
    unsigned a;
    asm("{ .reg .u64 t; cvta.to.shared.u64 t, %1; cvt.u32.u64 %0, t; }"
        : "=r"(a) : "l"(p));
    return a;
}
__device__ __forceinline__ unsigned long long lds64(unsigned addr) {
    unsigned long long v;
    asm volatile("ld.shared.b64 %0, [%1];" : "=l"(v) : "r"(addr));
    return v;
}
__device__ __forceinline__ void lds64x2(unsigned addr, unsigned long long& a,
                                        unsigned long long& b) {
    asm volatile("ld.shared.v2.b64 {%0, %1}, [%2];"
                 : "=l"(a), "=l"(b) : "r"(addr));
}
__device__ __forceinline__ void st_cluster_f32(unsigned saddr, unsigned rank, float v) {
    asm volatile(
        "{\n\t"
        ".reg .u32 ra;\n\t"
        "mapa.shared::cluster.u32 ra, %0, %1;\n\t"
        "st.shared::cluster.f32 [ra], %2;\n\t"
        "}" :: "r"(saddr), "r"(rank), "f"(v) : "memory");
}
__device__ __forceinline__ void mbar_init(unsigned addr, unsigned cnt) {
    asm volatile("mbarrier.init.shared.b64 [%0], %1;" :: "r"(addr), "r"(cnt)
                 : "memory");
}
__device__ __forceinline__ void mbar_arrive_cluster(unsigned addr, unsigned rank) {
    asm volatile(
        "{\n\t"
        ".reg .u32 ra;\n\t"
        "mapa.shared::cluster.u32 ra, %0, %1;\n\t"
        "mbarrier.arrive.release.cluster.shared::cluster.b64 _, [ra];\n\t"
        "}" :: "r"(addr), "r"(rank) : "memory");
}
__device__ __forceinline__ void mbar_wait_acq(unsigned addr, unsigned parity) {
    unsigned done;
    asm volatile(
        "{\n\t"
        ".reg .pred p;\n\t"
        "mbarrier.try_wait.parity.acquire.cluster.shared::cta.b64 p, [%1], %2;\n\t"
        "selp.b32 %0, 1, 0, p;\n\t"
        "}" : "=r"(done) : "r"(addr), "r"(parity) : "memory");
    if (!done) {
        asm volatile(
            "{\n\t"
            ".reg .pred P1;\n\t"
            "WL_%=:\n\t"
            "mbarrier.try_wait.parity.acquire.cluster.shared::cta.b64 P1, [%0], %1, 0x989680;\n\t"
            "@P1 bra.uni WD_%=;\n\t"
            "bra.uni WL_%=;\n\t"
            "WD_%=:\n\t"
            "}" :: "r"(addr), "r"(parity) : "memory");
    }
}
__device__ __forceinline__ unsigned my_cluster_rank() {
    unsigned r;
    asm("mov.u32 %0, %%cluster_ctarank;" : "=r"(r));
    return r;
}
__device__ __forceinline__ float sigf(float x) {
    return __fdividef(1.0f, 1.0f + __expf(-x));
}
__device__ __forceinline__ float tanhf_fast(float x) {
    float e = __expf(2.0f * x);
    return 1.0f - __fdividef(2.0f, e + 1.0f);
}
#define CLUSTER_SYNC_() do { \
    asm volatile("barrier.cluster.arrive.aligned;" ::: "memory"); \
    asm volatile("barrier.cluster.wait.aligned;"   ::: "memory"); } while (0)

// ---------------------------------------------------------------------------
// Kernel 1: g_gx[m][n] = embed[tokens[m]] . Wih[n] + bih[n]   (unchanged R16)
// ---------------------------------------------------------------------------
__global__ void __launch_bounds__(256)
gx_gemm_kernel(const int* __restrict__ tokens, const float* __restrict__ embed,
               const float* __restrict__ Wih, const float* __restrict__ bih) {
    __shared__ __align__(16) float2 As2[32 * 64];
    __shared__ __align__(16) float2 Bs2[32 * 64];

    const int tid = threadIdx.x;
    const int bm = blockIdx.x, bn = blockIdx.y;

    const int lr = tid & 63;
    const int lq = tid >> 6;
    const int tok = tokens[bm * 64 + lr];
    const float* Arow = embed + (size_t)tok * DIM;
    const float* Brow = Wih + (size_t)(bn * 64 + lr) * DIM;

    const int tn = tid & 15;
    const int tm = tid >> 4;
    const unsigned aBase = smem_u32(As2) + (unsigned)tm * 8u;
    const unsigned bBase = smem_u32(Bs2) + (unsigned)tn * 8u;

    unsigned long long acc[4][4];
#pragma unroll
    for (int i = 0; i < 4; i++)
#pragma unroll
        for (int j = 0; j < 4; j++) acc[i][j] = 0ull;

#pragma unroll 1
    for (int kc = 0; kc < 4; kc++) {
        __syncthreads();
#pragma unroll
        for (int s = 0; s < 4; s++) {
            const int kb = lq * 16 + s * 4;
            float4 a = *(const float4*)(Arow + kc * 64 + kb);
            float4 b = *(const float4*)(Brow + kc * 64 + kb);
            As2[(kb >> 1) * 64 + lr]       = make_float2(a.x, a.y);
            As2[((kb >> 1) + 1) * 64 + lr] = make_float2(a.z, a.w);
            Bs2[(kb >> 1) * 64 + lr]       = make_float2(b.x, b.y);
            Bs2[((kb >> 1) + 1) * 64 + lr] = make_float2(b.z, b.w);
        }
        __syncthreads();

#pragma unroll 8
        for (int k2 = 0; k2 < 32; k2++) {
            const unsigned off = (unsigned)k2 * 512u;
            unsigned long long a2[4], b2[4];
#pragma unroll
            for (int i = 0; i < 4; i++) a2[i] = lds64(aBase + off + i * 128u);
#pragma unroll
            for (int j = 0; j < 4; j++) b2[j] = lds64(bBase + off + j * 128u);
#pragma unroll
            for (int i = 0; i < 4; i++)
#pragma unroll
                for (int j = 0; j < 4; j++)
                    acc[i][j] = fma2(a2[i], b2[j], acc[i][j]);
        }
    }

    float bj[4];
#pragma unroll
    for (int j = 0; j < 4; j++) bj[j] = bih[bn * 64 + j * 16 + tn];
#pragma unroll
    for (int i = 0; i < 4; i++) {
        const size_t m = (size_t)bm * 64 + i * 16 + tm;
        float* orow = g_gx + m * G3 + bn * 64 + tn;
#pragma unroll
        for (int j = 0; j < 4; j++) {
            float2 s = upk2(acc[i][j]);
            orow[j * 16] = s.x + s.y + bj[j];
        }
    }
}

// ---------------------------------------------------------------------------
// Kernel 2 (FUSED, anti-phase): word GRU 512 steps + online pool + tail.
// 4-CTA cluster, CTA owns units [64r,64r+64); weights register-resident
// (384 threads x 64 f32x2). Batches b0/b1 processed in alternating phases;
// per-batch mbarriers give pre-satisfied (fast) waits because each batch's
// DSMEM exchange drains during the other batch's phase.
// ---------------------------------------------------------------------------
__global__ void __launch_bounds__(384, 1) __cluster_dims__(4, 1, 1)
gru_fused_kernel(const float* __restrict__ Whh, const float* __restrict__ bhh,
                 const float* __restrict__ uaw,
                 const float* __restrict__ sgWih, const float* __restrict__ sgbih,
                 const float* __restrict__ sgbhh, float* __restrict__ out) {
    __shared__ __align__(16) float hbuf[2][2][DIM];   // parity, batch, unit
    __shared__ __align__(16) float ghbF[192];
    __shared__ __align__(16) float gxbF[192];
    __shared__ __align__(16) float swua[DIM];
    __shared__ float2 pcs[2][2];          // [step parity][batch] softmax scales
    __shared__ float  sS[2];
    __shared__ __align__(8) unsigned long long mbar[2];

    const int tid = threadIdx.x;
    const int wid = tid >> 5, lane = tid & 31;
    const unsigned rank = my_cluster_rank();
    const int cid = blockIdx.x >> 2;
    const int b0 = cid * 2;

    const int row = tid >> 1;             // local gate row 0..191
    const int kh  = tid & 1;              // k half (lane bit -> shfl reduce)
    const int useg = row >> 6;
    const int uu   = row & 63;
    const int grow = useg * 256 + (int)rank * 64 + uu;

    unsigned long long w[64];
    {
        const float2* wr = (const float2*)(Whh + (size_t)grow * DIM + kh * 128);
#pragma unroll
        for (int i = 0; i < 64; i++) {
            float2 v = wr[i];
            w[i] = pk2(v.x, v.y);
        }
    }
    const float bias = bhh[grow];

    const unsigned hbase = smem_u32(hbuf);
    const unsigned mb0 = smem_u32(&mbar[0]);
    const unsigned mb1 = smem_u32(&mbar[1]);

    if (tid == 0) { mbar_init(mb0, 4); mbar_init(mb1, 4); }
    for (int i = tid; i < 2 * DIM; i += 384) ((float*)hbuf[0])[i] = 0.0f;
    if (tid < DIM) swua[tid] = uaw[tid];
    __syncthreads();
    CLUSTER_SYNC_();

    const float* gp0 = g_gx + (size_t)b0 * SEQL * G3 + grow;
    const float* gp1 = gp0 + (size_t)SEQL * G3;

    // per-(unit,batch) state in combine threads (tid < 64)
    float hreg0 = 0.0f, hprev0 = 0.0f, pacc0 = 0.0f;
    float hreg1 = 0.0f, hprev1 = 0.0f, pacc1 = 0.0f;
    // online softmax state in warp 4 lane 0
    float pm0 = -1e30f, ps0 = 0.0f, pm1 = -1e30f, ps1 = 0.0f;

    const unsigned long long one2 = pk2(1.0f, 1.0f);

#pragma unroll 1
    for (int t = 0; t < SEQL; t++) {
        const int par = t & 1;
        const unsigned wpar = (unsigned)(par ^ 1);   // (t-1)&1

        // ================= PHASE A : batch 0 =================
        if (t) mbar_wait_acq(mb0, wpar);
        float xg0 = 0.0f;
        if (kh) xg0 = __ldg(gp0);
        gp0 += G3;
        {
            const unsigned hA = hbase + (unsigned)((par * 2) * DIM + kh * 128) * 4u;
            unsigned long long c0 = 0, c1 = 0, c2 = 0, c3 = 0;
            unsigned long long p0, q0, p1, q1;
            lds64x2(hA, p0, q0);
            lds64x2(hA + 16u, p1, q1);
#pragma unroll
            for (int i = 0; i < 32; i++) {
                unsigned long long np = 0, nq = 0;
                if (i < 30) lds64x2(hA + (unsigned)(i + 2) * 16u, np, nq);
                if (i & 1) { c2 = fma2(w[2 * i], p0, c2); c3 = fma2(w[2 * i + 1], q0, c3); }
                else       { c0 = fma2(w[2 * i], p0, c0); c1 = fma2(w[2 * i + 1], q0, c1); }
                p0 = p1; q0 = q1; p1 = np; q1 = nq;
            }
            c0 = fma2(one2, c2, c0);
            c1 = fma2(one2, c3, c1);
            c0 = fma2(one2, c1, c0);
            float2 f = upk2(c0);
            float s = f.x + f.y;
            s += __shfl_xor_sync(0xffffffffu, s, 1);
            if (kh == 0) ghbF[row] = s + bias;
            else         gxbF[row] = xg0;
        }
        __syncthreads();
        if (tid < 64) {
            if (t >= 2) {
                float2 c = pcs[par ^ 1][0];
                pacc0 = pacc0 * c.x + c.y * hprev0;
            }
            hprev0 = hreg0;
            float r = sigf(gxbF[tid] + ghbF[tid]);
            float z = sigf(gxbF[64 + tid] + ghbF[64 + tid]);
            float n = tanhf_fast(gxbF[128 + tid] + r * ghbF[128 + tid]);
            float h = (1.0f - z) * n + z * hreg0;
            hreg0 = h;
            const unsigned a = hbase +
                (unsigned)(((par ^ 1) * 2) * DIM + (int)rank * 64 + tid) * 4u;
#pragma unroll
            for (unsigned rk = 0; rk < 4; rk++) st_cluster_f32(a, rk, h);
        }
        if (wid == 4 && t) {    // logit on h_t = hbuf[par][0] (stable)
            const float* hb = &hbuf[par][0][0];
            float l = 0.0f;
#pragma unroll
            for (int j = 0; j < 8; j++)
                l += hb[lane + 32 * j] * swua[lane + 32 * j];
#pragma unroll
            for (int o = 16; o > 0; o >>= 1)
                l += __shfl_xor_sync(0xffffffffu, l, o);
            if (lane == 0) {
                float mn = fmaxf(pm0, l);
                float e0 = __expf(pm0 - mn);
                float e1 = __expf(l - mn);
                ps0 = ps0 * e0 + e1;
                pm0 = mn;
                pcs[par][0] = make_float2(e0, e1);
            }
        }
        __syncthreads();
        if (lane == 0 && wid >= 8) mbar_arrive_cluster(mb0, (unsigned)(wid - 8));

        // ================= PHASE B : batch 1 =================
        if (t) mbar_wait_acq(mb1, wpar);
        float xg1 = 0.0f;
        if (kh) xg1 = __ldg(gp1);
        gp1 += G3;
        {
            const unsigned hA = hbase + (unsigned)((par * 2 + 1) * DIM + kh * 128) * 4u;
            unsigned long long c0 = 0, c1 = 0, c2 = 0, c3 = 0;
            unsigned long long p0, q0, p1, q1;
            lds64x2(hA, p0, q0);
            lds64x2(hA + 16u, p1, q1);
#pragma unroll
            for (int i = 0; i < 32; i++) {
                unsigned long long np = 0, nq = 0;
                if (i < 30) lds64x2(hA + (unsigned)(i + 2) * 16u, np, nq);
                if (i & 1) { c2 = fma2(w[2 * i], p0, c2); c3 = fma2(w[2 * i + 1], q0, c3); }
                else       { c0 = fma2(w[2 * i], p0, c0); c1 = fma2(w[2 * i + 1], q0, c1); }
                p0 = p1; q0 = q1; p1 = np; q1 = nq;
            }
            c0 = fma2(one2, c2, c0);
            c1 = fma2(one2, c3, c1);
            c0 = fma2(one2, c1, c0);
            float2 f = upk2(c0);
            float s = f.x + f.y;
            s += __shfl_xor_sync(0xffffffffu, s, 1);
            if (kh == 0) ghbF[row] = s + bias;
            else         gxbF[row] = xg1;
        }
        __syncthreads();
        if (tid < 64) {
            if (t >= 2) {
                float2 c = pcs[par ^ 1][1];
                pacc1 = pacc1 * c.x + c.y * hprev1;
            }
            hprev1 = hreg1;
            float r = sigf(gxbF[tid] + ghbF[tid]);
            float z = sigf(gxbF[64 + tid] + ghbF[64 + tid]);
            float n = tanhf_fast(gxbF[128 + tid] + r * ghbF[128 + tid]);
            float h = (1.0f - z) * n + z * hreg1;
            hreg1 = h;
            const unsigned a = hbase +
                (unsigned)(((par ^ 1) * 2 + 1) * DIM + (int)rank * 64 + tid) * 4u;
#pragma unroll
            for (unsigned rk = 0; rk < 4; rk++) st_cluster_f32(a, rk, h);
        }
        if (wid == 4 && t) {
            const float* hb = &hbuf[par][1][0];
            float l = 0.0f;
#pragma unroll
            for (int j = 0; j < 8; j++)
                l += hb[lane + 32 * j] * swua[lane + 32 * j];
#pragma unroll
            for (int o = 16; o > 0; o >>= 1)
                l += __shfl_xor_sync(0xffffffffu, l, o);
            if (lane == 0) {
                float mn = fmaxf(pm1, l);
                float e0 = __expf(pm1 - mn);
                float e1 = __expf(l - mn);
                ps1 = ps1 * e0 + e1;
                pm1 = mn;
                pcs[par][1] = make_float2(e0, e1);
            }
        }
        __syncthreads();
        if (lane == 0 && wid >= 8) mbar_arrive_cluster(mb1, (unsigned)(wid - 8));
    }

    // wait for final exchanges (step 511 -> parity 1); S_512 in hbuf[0]
    mbar_wait_acq(mb0, 1u);
    mbar_wait_acq(mb1, 1u);
    __syncthreads();

    // pending pool term S_511 (pcs[1][bi]) applied to hprev
    if (tid < 64) {
        float2 c = pcs[1][0];
        pacc0 = pacc0 * c.x + c.y * hprev0;
        c = pcs[1][1];
        pacc1 = pacc1 * c.x + c.y * hprev1;
    }
    // final logit on S_512 (hbuf[0])
    if (wid == 4) {
#pragma unroll
        for (int bi = 0; bi < 2; bi++) {
            const float* hb = &hbuf[0][bi][0];
            float l = 0.0f;
#pragma unroll
            for (int j = 0; j < 8; j++)
                l += hb[lane + 32 * j] * swua[lane + 32 * j];
#pragma unroll
            for (int o = 16; o > 0; o >>= 1)
                l += __shfl_xor_sync(0xffffffffu, l, o);
            if (lane == 0) {
                float pm = bi ? pm1 : pm0;
                float ps = bi ? ps1 : ps0;
                float mn = fmaxf(pm, l);
                float e0 = __expf(pm - mn);
                float e1 = __expf(l - mn);
                ps = ps * e0 + e1;
                pcs[0][bi] = make_float2(e0, e1);
                sS[bi] = ps;
            }
        }
    }
    __syncthreads();

    // finalize utt, broadcast into hbuf[1][bi] of all CTAs
    if (tid < 64) {
        float2 c = pcs[0][0];
        pacc0 = pacc0 * c.x + c.y * hreg0;
        float utt0 = __fdividef(pacc0, sS[0]);
        c = pcs[0][1];
        pacc1 = pacc1 * c.x + c.y * hreg1;
        float utt1 = __fdividef(pacc1, sS[1]);
        const unsigned a0 = hbase + (unsigned)(2 * DIM + (int)rank * 64 + tid) * 4u;
        const unsigned a1 = a0 + DIM * 4u;
#pragma unroll
        for (unsigned rk = 0; rk < 4; rk++) {
            st_cluster_f32(a0, rk, utt0);
            st_cluster_f32(a1, rk, utt1);
        }
    }
    CLUSTER_SYNC_();

    // ---- sentence GRU tail (sg_Whh dead; T=1 pool = identity) ----
    {
        const float* xs0 = &hbuf[1][0][0];
        const float* xs1 = &hbuf[1][1][0];
        const float4* Wr = (const float4*)(sgWih + (size_t)grow * DIM + kh * 128);
        float a0 = 0.0f, a1 = 0.0f;
#pragma unroll 8
        for (int i = 0; i < 32; i++) {
            float4 w4 = __ldg(Wr + i);
            const int k0 = kh * 128 + i * 4;
            a0 += w4.x * xs0[k0] + w4.y * xs0[k0 + 1]
                + w4.z * xs0[k0 + 2] + w4.w * xs0[k0 + 3];
            a1 += w4.x * xs1[k0] + w4.y * xs1[k0 + 1]
                + w4.z * xs1[k0 + 2] + w4.w * xs1[k0 + 3];
        }
        a0 += __shfl_xor_sync(0xffffffffu, a0, 1);
        a1 += __shfl_xor_sync(0xffffffffu, a1, 1);
        if (kh == 0) {
            float bg = sgbih[grow];
            ghbF[row] = a0 + bg;
            gxbF[row] = a1 + bg;
        }
    }
    __syncthreads();

    if (tid < 128) {
        const int u = tid & 63;
        const int bi = tid >> 6;
        const int U = (int)rank * 64 + u;
        const float* A = bi ? gxbF : ghbF;
        float r = sigf(A[u] + sgbhh[U]);
        float z = sigf(A[64 + u] + sgbhh[DIM + U]);
        float n = tanhf_fast(A[128 + u] + r * sgbhh[2 * DIM + U]);
        out[(b0 + bi) * DIM + U] = (1.0f - z) * n;
    }
    CLUSTER_SYNC_();   // keep smem alive until peers' remote ops landed
}

// ---------------------------------------------------------------------------
extern "C" void kernel_launch(void* const* d_in, const int* in_sizes, int n_in,
                              void* d_out, int out_size) {
    const int*   tokens = (const int*)d_in[0];
    const float* embed  = (const float*)d_in[1];
    const float* wgWih  = (const float*)d_in[2];
    const float* wgWhh  = (const float*)d_in[3];
    const float* wgbih  = (const float*)d_in[4];
    const float* wgbhh  = (const float*)d_in[5];
    const float* uaw    = (const float*)d_in[6];
    // d_in[7] = ua_b (dead: softmax shift-invariant)
    const float* sgWih  = (const float*)d_in[8];
    // d_in[9] = sg_Whh (dead: h0 = 0), d_in[12..13] = da_w/da_b (dead: T=1)
    const float* sgbih  = (const float*)d_in[10];
    const float* sgbhh  = (const float*)d_in[11];
    float* out = (float*)d_out;

    dim3 ggrid(512, 12);
    gx_gemm_kernel<<<ggrid, 256>>>(tokens, embed, wgWih, wgbih);
    gru_fused_kernel<<<128, 384>>>(wgWhh, wgbhh, uaw, sgWih, sgbih, sgbhh, out);
}